// round 12
// baseline (speedup 1.0000x reference)
#include <cuda_runtime.h>
#include <cstdint>

#define NIMG 96
#define NB_B 32
#define NC_C 3
#define NH 1024
#define NW 1024
#define WR 513
#define WPAD 516
#define NBANDS 16
#define FEAT 256
#define FIN 144

// ---------------- scratch (device globals; zero-initialized at load) ----------------
__device__ float2 g_spec[(size_t)NIMG * NH * WPAD];   // ~406 MB row-FFT spectra, row stride WPAD
__device__ float g_s1[NIMG * NBANDS];
__device__ float g_s2[NIMG * NBANDS];
__device__ unsigned int g_mx[NIMG * NBANDS];
__device__ float g_cnt[NBANDS];

// ---------------- helpers ----------------
__device__ __forceinline__ float2 cmul(float2 a, float2 b) {
    return make_float2(a.x * b.x - a.y * b.y, a.x * b.y + a.y * b.x);
}
// reverse 5 base-4 digits of a 10-bit index
__device__ __forceinline__ int dr10(int n) {
    return ((n & 3) << 8) | ((n & 12) << 4) | (n & 48) | ((n >> 4) & 12) | ((n >> 8) & 3);
}
// FMA-pipe sqrt (avoids MUFU): bit-trick rsqrt + 3 Newton steps, then x*rsqrt(x)
__device__ __forceinline__ float fast_sqrt(float x) {
    float xh = 0.5f * x;
    float y = __uint_as_float(0x5f3759dfu - (__float_as_uint(x) >> 1));
    y = y * (1.5f - xh * y * y);
    y = y * (1.5f - xh * y * y);
    y = y * (1.5f - xh * y * y);
    return x * y;
}
__device__ __forceinline__ int band_of(float r) {
    const float mr = 0.70710678118654752440f;  // == sqrtf(0.5f), correctly rounded
    int bin = 0;
#pragma unroll
    for (int j = 1; j <= 16; j++) bin += (r >= __fmul_rn(mr, (float)j * 0.0625f)) ? 1 : 0;
    return bin;  // 16 == excluded corner band
}

// in-place radix-4 DIT butterfly on one 1024-pt array, one butterfly (index k, stage s)
__device__ __forceinline__ void r4_bfly(float2* S, int k, int s, const float2* TW) {
    int q = 1 << (2 * s);
    int pos = k & (q - 1);
    int base = ((k >> (2 * s)) << (2 * s + 2)) + pos;
    float2 w1 = TW[pos << (8 - 2 * s)];
    float2 w2 = cmul(w1, w1);
    float2 w3 = cmul(w2, w1);
    float2 x0 = S[base];
    float2 x1 = cmul(S[base + q], w1);
    float2 x2 = cmul(S[base + 2 * q], w2);
    float2 x3 = cmul(S[base + 3 * q], w3);
    float2 A = make_float2(x0.x + x2.x, x0.y + x2.y);
    float2 Bv = make_float2(x0.x - x2.x, x0.y - x2.y);
    float2 Cv = make_float2(x1.x + x3.x, x1.y + x3.y);
    float2 Dv = make_float2(x1.y - x3.y, -(x1.x - x3.x));  // -i*(x1-x3)
    S[base] = make_float2(A.x + Cv.x, A.y + Cv.y);
    S[base + q] = make_float2(Bv.x + Dv.x, Bv.y + Dv.y);
    S[base + 2 * q] = make_float2(A.x - Cv.x, A.y - Cv.y);
    S[base + 3 * q] = make_float2(Bv.x - Dv.x, Bv.y - Dv.y);
}

// ---------------- kernel 0: zero accumulators ----------------
__global__ void k_zero(void) {
    int t = blockIdx.x * blockDim.x + threadIdx.x;
    if (t < NIMG * NBANDS) {
        g_s1[t] = 0.f;
        g_s2[t] = 0.f;
        g_mx[t] = 0u;
    }
    if (t < NBANDS) g_cnt[t] = 0.f;
}

// ---------------- kernel 1: per-band pixel counts (image-independent) ----------------
__global__ __launch_bounds__(256) void k_counts(void) {
    __shared__ int h[NBANDS];
    int t = threadIdx.x;
    int y = blockIdx.x;
    if (t < NBANDS) h[t] = 0;
    __syncthreads();
    int yy = (y < 512) ? y : y - 1024;
    float vf = (float)yy * 0.0009765625f;
    float vv = __fmul_rn(vf, vf);
    for (int u = t; u < WR; u += 256) {
        float uf = (float)u * 0.0009765625f;
        float r = __fsqrt_rn(__fadd_rn(__fmul_rn(uf, uf), vv));
        int bin = band_of(r);
        if (bin <= 15) atomicAdd(&h[bin], 1);
    }
    __syncthreads();
    if (t < NBANDS) atomicAdd(&g_cnt[t], (float)h[t]);
}

// ---------------- kernel 2: row FFTs (two real rows per complex FFT) ----------------
__global__ __launch_bounds__(256) void k_rowfft(const float* __restrict__ x) {
    __shared__ float2 S[1024];
    __shared__ float2 TW[256];
    int t = threadIdx.x;
    int img = blockIdx.y;
    int rp = blockIdx.x;  // row pair: rows 2rp, 2rp+1
    {
        float sv, cv;
        sincospif(-2.0f * (float)t / 1024.0f, &sv, &cv);
        TW[t] = make_float2(cv, sv);
    }
    const float* r0 = x + ((size_t)img * NH + 2 * rp) * NW;
    const float* r1 = r0 + NW;
#pragma unroll
    for (int j = 0; j < 4; j++) {
        int n = t + j * 256;
        S[dr10(n)] = make_float2(r0[n], r1[n]);  // z = a + i b
    }
    __syncthreads();
#pragma unroll
    for (int s = 0; s < 5; s++) {
        r4_bfly(S, t, s, TW);
        __syncthreads();
    }
    // unpack two real spectra, write transpose-friendly padded layout
    size_t o0 = ((size_t)img * NH + 2 * rp) * WPAD;
#pragma unroll
    for (int j = 0; j < 3; j++) {
        int u = t + j * 256;
        if (u <= 512) {
            float2 Zk = S[u];
            float2 Zm = S[(1024 - u) & 1023];
            float ar = 0.5f * (Zk.x + Zm.x), ai = 0.5f * (Zk.y - Zm.y);
            float dr_ = 0.5f * (Zk.x - Zm.x), di = 0.5f * (Zk.y + Zm.y);
            g_spec[o0 + u] = make_float2(ar, ai);            // row 2rp
            g_spec[o0 + WPAD + u] = make_float2(di, -dr_);   // row 2rp+1
        }
    }
}

// ---------------- kernel 3: column FFTs (4 columns/block) + band stats ----------------
__global__ __launch_bounds__(512) void k_colfft(void) {
    __shared__ float2 S[4][1024];
    __shared__ float2 TW[256];
    __shared__ float hs1[NBANDS], hs2[NBANDS];
    __shared__ unsigned int hmx[NBANDS];
    int t = threadIdx.x;
    int img = blockIdx.y;
    int u0 = blockIdx.x * 4;
    if (t < 256) {
        float sv, cv;
        sincospif(-2.0f * (float)t / 1024.0f, &sv, &cv);
        TW[t] = make_float2(cv, sv);
    }
    if (t < NBANDS) {
        hs1[t] = 0.f;
        hs2[t] = 0.f;
        hmx[t] = 0u;
    }
    // coalesced float4 loads (row stride 4128 B = 129*32B), digit-reversed scatter into smem
    size_t ibase = (size_t)img * NH * WPAD + u0;
#pragma unroll
    for (int j = 0; j < 4; j++) {
        int p = t + j * 512;
        int y = p >> 1;
        int h = p & 1;
        const float4 v = *reinterpret_cast<const float4*>(&g_spec[ibase + (size_t)y * WPAD + 2 * h]);
        int yd = dr10(y);
        S[2 * h][yd] = make_float2(v.x, v.y);
        S[2 * h + 1][yd] = make_float2(v.z, v.w);
    }
    __syncthreads();
#pragma unroll
    for (int s = 0; s < 5; s++) {
        int k = t & 255;
        int cp = t >> 8;  // 0 -> cols 0,1 ; 1 -> cols 2,3
#pragma unroll
        for (int cc = 0; cc < 2; cc++) r4_bfly(S[cp * 2 + cc], k, s, TW);
        __syncthreads();
    }
    // band statistics over the 4 columns (skip padded u>512)
    float uu[4];
#pragma unroll
    for (int c = 0; c < 4; c++) {
        float uf = (float)(u0 + c) * 0.0009765625f;
        uu[c] = __fmul_rn(uf, uf);
    }
#pragma unroll
    for (int j = 0; j < 8; j++) {
        int c = j >> 1;
        int u = u0 + c;
        int y = (j & 1) * 512 + t;
        float2 z = S[c][y];
        float m2 = fmaxf(z.x * z.x + z.y * z.y, 1e-35f);
        float mag = fast_sqrt(m2) * (1.0f / 1024.0f);       // ortho norm
        float m2s = m2 * (1.0f / 1048576.0f);
        int yy = (y < 512) ? y : y - 1024;
        float vf = (float)yy * 0.0009765625f;
        float r = __fsqrt_rn(__fadd_rn(uu[c], __fmul_rn(vf, vf)));
        int bin = band_of(r);
        bool good = (u <= 512) && (bin <= 15);
        float magv = good ? mag : 0.f;
        float m2v = good ? m2s : 0.f;
        unsigned mxv = good ? __float_as_uint(mag) : 0u;
        int bin0 = __shfl_sync(0xffffffffu, bin, 0);
        bool uni = __all_sync(0xffffffffu, good && (bin == bin0));
        if (uni) {
#pragma unroll
            for (int o = 16; o; o >>= 1) {
                magv += __shfl_xor_sync(0xffffffffu, magv, o);
                m2v += __shfl_xor_sync(0xffffffffu, m2v, o);
                unsigned om = __shfl_xor_sync(0xffffffffu, mxv, o);
                mxv = (om > mxv) ? om : mxv;
            }
            if ((t & 31) == 0) {
                atomicAdd(&hs1[bin0], magv);
                atomicAdd(&hs2[bin0], m2v);
                atomicMax(&hmx[bin0], mxv);
            }
        } else if (good) {
            atomicAdd(&hs1[bin], magv);
            atomicAdd(&hs2[bin], m2v);
            atomicMax(&hmx[bin], mxv);
        }
    }
    __syncthreads();
    if (t < NBANDS) {
        atomicAdd(&g_s1[img * NBANDS + t], hs1[t]);
        atomicAdd(&g_s2[img * NBANDS + t], hs2[t]);
        atomicMax(&g_mx[img * NBANDS + t], hmx[t]);
    }
}

// ---------------- kernel 4: features -> MLP -> LayerNorm ----------------
__device__ __forceinline__ float block_sum_256(float v, float* red, int t) {
#pragma unroll
    for (int o = 16; o; o >>= 1) v += __shfl_xor_sync(0xffffffffu, v, o);
    if ((t & 31) == 0) red[t >> 5] = v;
    __syncthreads();
    if (t < 8) {
        float w = red[t];
#pragma unroll
        for (int o = 4; o; o >>= 1) w += __shfl_xor_sync(0xffu, w, o);
        if (t == 0) red[0] = w;
    }
    __syncthreads();
    float r = red[0];
    __syncthreads();
    return r;
}

__global__ __launch_bounds__(256) void k_head(
    const float* __restrict__ W1, const float* __restrict__ b1,
    const float* __restrict__ W2, const float* __restrict__ b2,
    const float* __restrict__ gamma, const float* __restrict__ beta,
    float* __restrict__ out) {
    __shared__ float feat[FIN];
    __shared__ float h1[FEAT];
    __shared__ float red[8];
    int b = blockIdx.x;
    int t = threadIdx.x;
    if (t < FIN) {
        int k = t / 9;
        int rem = t - k * 9;
        int s = rem / 3;
        int c = rem - s * 3;
        int img = b * 3 + c;
        float cnt = g_cnt[k];
        float denom = cnt + 1e-8f;
        float s1 = g_s1[img * NBANDS + k];
        float s2 = g_s2[img * NBANDS + k];
        float mean = s1 / denom;
        float var = (s2 - 2.0f * mean * s1 + cnt * mean * mean) / denom;
        var = fmaxf(var, 0.0f);
        float mx = fmaxf(__uint_as_float(g_mx[img * NBANDS + k]), 0.0f);
        feat[t] = (s == 0) ? mean : ((s == 1) ? mx : sqrtf(var));
    }
    __syncthreads();
    float acc = b1[t];
#pragma unroll 4
    for (int i = 0; i < FIN; i++) acc = fmaf(feat[i], W1[i * FEAT + t], acc);
    acc = (acc >= 0.0f) ? acc : 0.2f * acc;
    h1[t] = acc;
    __syncthreads();
    float acc2 = b2[t];
#pragma unroll 4
    for (int i = 0; i < FEAT; i++) acc2 = fmaf(h1[i], W2[i * FEAT + t], acc2);
    float mu = block_sum_256(acc2, red, t) * (1.0f / 256.0f);
    float d = acc2 - mu;
    float va = block_sum_256(d * d, red, t) * (1.0f / 256.0f);
    out[b * FEAT + t] = d * rsqrtf(va + 1e-5f) * gamma[t] + beta[t];
}

// ---------------- launch ----------------
extern "C" void kernel_launch(void* const* d_in, const int* in_sizes, int n_in,
                              void* d_out, int out_size) {
    const float* x = (const float*)d_in[0];
    const float* W1 = (const float*)d_in[1];
    const float* b1 = (const float*)d_in[2];
    const float* W2 = (const float*)d_in[3];
    const float* b2 = (const float*)d_in[4];
    const float* gamma = (const float*)d_in[5];
    const float* beta = (const float*)d_in[6];
    float* out = (float*)d_out;
    (void)in_sizes; (void)n_in; (void)out_size;

    k_zero<<<6, 256>>>();
    k_counts<<<NH, 256>>>();
    k_rowfft<<<dim3(512, NIMG), 256>>>(x);
    k_colfft<<<dim3(129, NIMG), 512>>>();
    k_head<<<NB_B, 256>>>(W1, b1, W2, b2, gamma, beta, out);
}

// round 13
// speedup vs baseline: 1.3690x; 1.3690x over previous
#include <cuda_runtime.h>
#include <cstdint>

#define NIMG 96
#define NB_B 32
#define NC_C 3
#define NH 1024
#define NW 1024
#define WR 513
#define WPAD 516
#define NBANDS 16
#define FEAT 256
#define FIN 144

// ---------------- scratch (device globals; zero-initialized at load) ----------------
__device__ float2 g_spec[(size_t)NIMG * NH * WPAD];   // ~406 MB row-FFT spectra, row stride WPAD
__device__ float g_s1[NIMG * NBANDS];
__device__ float g_s2[NIMG * NBANDS];
__device__ unsigned int g_mx[NIMG * NBANDS];
__device__ float g_cnt[NBANDS];

// ---------------- helpers ----------------
__device__ __forceinline__ float2 cmul(float2 a, float2 b) {
    return make_float2(a.x * b.x - a.y * b.y, a.x * b.y + a.y * b.x);
}
// reverse 5 base-4 digits of a 10-bit index
__device__ __forceinline__ int dr10(int n) {
    return ((n & 3) << 8) | ((n & 12) << 4) | (n & 48) | ((n >> 4) & 12) | ((n >> 8) & 3);
}
// bank-conflict-killing XOR swizzle: permutes low 4 bits by high bits.
// Verified conflict-free for: dr10 scatter, all 5 radix-4 stages, linear reads.
__device__ __forceinline__ int swz(int i) {
    int h1 = (i >> 4) & 3;
    int h2 = (i >> 6) & 3;
    int h3 = (i >> 8) & 3;
    return i ^ (h1 ^ h2) ^ ((h1 ^ h3) << 2);
}
// FMA-pipe sqrt (avoids MUFU): bit-trick rsqrt + 3 Newton steps, then x*rsqrt(x)
__device__ __forceinline__ float fast_sqrt(float x) {
    float xh = 0.5f * x;
    float y = __uint_as_float(0x5f3759dfu - (__float_as_uint(x) >> 1));
    y = y * (1.5f - xh * y * y);
    y = y * (1.5f - xh * y * y);
    y = y * (1.5f - xh * y * y);
    return x * y;
}
__device__ __forceinline__ int band_of(float r) {
    const float mr = 0.70710678118654752440f;  // == sqrtf(0.5f), correctly rounded
    int bin = 0;
#pragma unroll
    for (int j = 1; j <= 16; j++) bin += (r >= __fmul_rn(mr, (float)j * 0.0625f)) ? 1 : 0;
    return bin;  // 16 == excluded corner band
}

// stage-local twiddle tables: TW_s[pos] = exp(-2*pi*i*pos/4^(s+1)), offsets (4^s-1)/3
// total entries: 1+4+16+64+256 = 341; consecutive entries -> conflict-free reads.
__device__ __forceinline__ void build_tw(float2* TW, int t, int nthreads) {
    for (int e = t; e < 341; e += nthreads) {
        int pos, den;
        if (e < 1)       { pos = e;       den = 4; }
        else if (e < 5)  { pos = e - 1;   den = 16; }
        else if (e < 21) { pos = e - 5;   den = 64; }
        else if (e < 85) { pos = e - 21;  den = 256; }
        else             { pos = e - 85;  den = 1024; }
        float sv, cv;
        sincospif(-2.0f * (float)pos / (float)den, &sv, &cv);
        TW[e] = make_float2(cv, sv);
    }
}

// in-place radix-4 DIT butterfly (swizzled addressing, stage-local twiddles)
__device__ __forceinline__ void r4_bfly(float2* S, int k, int s, const float2* TW) {
    int q = 1 << (2 * s);
    int pos = k & (q - 1);
    int base = ((k >> (2 * s)) << (2 * s + 2)) + pos;
    int i0 = swz(base);
    int i1 = swz(base + q);
    int i2 = swz(base + 2 * q);
    int i3 = swz(base + 3 * q);
    float2 x0 = S[i0];
    float2 x1 = S[i1];
    float2 x2 = S[i2];
    float2 x3 = S[i3];
    if (s > 0) {  // s is a compile-time constant in the unrolled loops
        const float2* TWs = TW + (q - 1) / 3;
        float2 w1 = TWs[pos];
        float2 w2 = cmul(w1, w1);
        float2 w3 = cmul(w2, w1);
        x1 = cmul(x1, w1);
        x2 = cmul(x2, w2);
        x3 = cmul(x3, w3);
    }
    float2 A = make_float2(x0.x + x2.x, x0.y + x2.y);
    float2 Bv = make_float2(x0.x - x2.x, x0.y - x2.y);
    float2 Cv = make_float2(x1.x + x3.x, x1.y + x3.y);
    float2 Dv = make_float2(x1.y - x3.y, -(x1.x - x3.x));  // -i*(x1-x3)
    S[i0] = make_float2(A.x + Cv.x, A.y + Cv.y);
    S[i1] = make_float2(Bv.x + Dv.x, Bv.y + Dv.y);
    S[i2] = make_float2(A.x - Cv.x, A.y - Cv.y);
    S[i3] = make_float2(Bv.x - Dv.x, Bv.y - Dv.y);
}

// ---------------- kernel 0: zero accumulators ----------------
__global__ void k_zero(void) {
    int t = blockIdx.x * blockDim.x + threadIdx.x;
    if (t < NIMG * NBANDS) {
        g_s1[t] = 0.f;
        g_s2[t] = 0.f;
        g_mx[t] = 0u;
    }
    if (t < NBANDS) g_cnt[t] = 0.f;
}

// ---------------- kernel 1: per-band pixel counts (image-independent) ----------------
__global__ __launch_bounds__(256) void k_counts(void) {
    __shared__ int h[NBANDS];
    int t = threadIdx.x;
    int y = blockIdx.x;
    if (t < NBANDS) h[t] = 0;
    __syncthreads();
    int yy = (y < 512) ? y : y - 1024;
    float vf = (float)yy * 0.0009765625f;
    float vv = __fmul_rn(vf, vf);
    for (int u = t; u < WR; u += 256) {
        float uf = (float)u * 0.0009765625f;
        float r = __fsqrt_rn(__fadd_rn(__fmul_rn(uf, uf), vv));
        int bin = band_of(r);
        if (bin <= 15) atomicAdd(&h[bin], 1);
    }
    __syncthreads();
    if (t < NBANDS) atomicAdd(&g_cnt[t], (float)h[t]);
}

// ---------------- kernel 2: row FFTs (two real rows per complex FFT) ----------------
__global__ __launch_bounds__(256) void k_rowfft(const float* __restrict__ x) {
    __shared__ float2 S[1024];
    __shared__ float2 TW[341];
    int t = threadIdx.x;
    int img = blockIdx.y;
    int rp = blockIdx.x;  // row pair: rows 2rp, 2rp+1
    build_tw(TW, t, 256);
    const float* r0 = x + ((size_t)img * NH + 2 * rp) * NW;
    const float* r1 = r0 + NW;
#pragma unroll
    for (int j = 0; j < 4; j++) {
        int n = t + j * 256;
        S[swz(dr10(n))] = make_float2(r0[n], r1[n]);  // z = a + i b
    }
    __syncthreads();
#pragma unroll
    for (int s = 0; s < 5; s++) {
        r4_bfly(S, t, s, TW);
        __syncthreads();
    }
    // unpack two real spectra, write transpose-friendly padded layout
    size_t o0 = ((size_t)img * NH + 2 * rp) * WPAD;
#pragma unroll
    for (int j = 0; j < 3; j++) {
        int u = t + j * 256;
        if (u <= 512) {
            float2 Zk = S[swz(u)];
            float2 Zm = S[swz((1024 - u) & 1023)];
            float ar = 0.5f * (Zk.x + Zm.x), ai = 0.5f * (Zk.y - Zm.y);
            float dr_ = 0.5f * (Zk.x - Zm.x), di = 0.5f * (Zk.y + Zm.y);
            g_spec[o0 + u] = make_float2(ar, ai);            // row 2rp
            g_spec[o0 + WPAD + u] = make_float2(di, -dr_);   // row 2rp+1
        }
    }
}

// ---------------- kernel 3: column FFTs (4 columns/block) + band stats ----------------
__global__ __launch_bounds__(512) void k_colfft(void) {
    __shared__ float2 S[4][1024];
    __shared__ float2 TW[341];
    __shared__ float hs1[NBANDS], hs2[NBANDS];
    __shared__ unsigned int hmx[NBANDS];
    int t = threadIdx.x;
    int img = blockIdx.y;
    int u0 = blockIdx.x * 4;
    build_tw(TW, t, 512);
    if (t < NBANDS) {
        hs1[t] = 0.f;
        hs2[t] = 0.f;
        hmx[t] = 0u;
    }
    // coalesced float4 loads (row stride 4128 B = 129*32B), digit-reversed swizzled scatter
    size_t ibase = (size_t)img * NH * WPAD + u0;
#pragma unroll
    for (int j = 0; j < 4; j++) {
        int p = t + j * 512;
        int y = p >> 1;
        int h = p & 1;
        const float4 v = *reinterpret_cast<const float4*>(&g_spec[ibase + (size_t)y * WPAD + 2 * h]);
        int yd = swz(dr10(y));
        S[2 * h][yd] = make_float2(v.x, v.y);
        S[2 * h + 1][yd] = make_float2(v.z, v.w);
    }
    __syncthreads();
#pragma unroll
    for (int s = 0; s < 5; s++) {
        int k = t & 255;
        int cp = t >> 8;  // 0 -> cols 0,1 ; 1 -> cols 2,3
#pragma unroll
        for (int cc = 0; cc < 2; cc++) r4_bfly(S[cp * 2 + cc], k, s, TW);
        __syncthreads();
    }
    // band statistics over the 4 columns (skip padded u>512)
    float uu[4];
#pragma unroll
    for (int c = 0; c < 4; c++) {
        float uf = (float)(u0 + c) * 0.0009765625f;
        uu[c] = __fmul_rn(uf, uf);
    }
#pragma unroll
    for (int j = 0; j < 8; j++) {
        int c = j >> 1;
        int u = u0 + c;
        int y = (j & 1) * 512 + t;
        float2 z = S[c][swz(y)];
        float m2 = fmaxf(z.x * z.x + z.y * z.y, 1e-35f);
        float mag = fast_sqrt(m2) * (1.0f / 1024.0f);       // ortho norm
        float m2s = m2 * (1.0f / 1048576.0f);
        int yy = (y < 512) ? y : y - 1024;
        float vf = (float)yy * 0.0009765625f;
        float r = __fsqrt_rn(__fadd_rn(uu[c], __fmul_rn(vf, vf)));
        int bin = band_of(r);
        bool good = (u <= 512) && (bin <= 15);
        float magv = good ? mag : 0.f;
        float m2v = good ? m2s : 0.f;
        unsigned mxv = good ? __float_as_uint(mag) : 0u;
        int bin0 = __shfl_sync(0xffffffffu, bin, 0);
        bool uni = __all_sync(0xffffffffu, good && (bin == bin0));
        if (uni) {
#pragma unroll
            for (int o = 16; o; o >>= 1) {
                magv += __shfl_xor_sync(0xffffffffu, magv, o);
                m2v += __shfl_xor_sync(0xffffffffu, m2v, o);
                unsigned om = __shfl_xor_sync(0xffffffffu, mxv, o);
                mxv = (om > mxv) ? om : mxv;
            }
            if ((t & 31) == 0) {
                atomicAdd(&hs1[bin0], magv);
                atomicAdd(&hs2[bin0], m2v);
                atomicMax(&hmx[bin0], mxv);
            }
        } else if (good) {
            atomicAdd(&hs1[bin], magv);
            atomicAdd(&hs2[bin], m2v);
            atomicMax(&hmx[bin], mxv);
        }
    }
    __syncthreads();
    if (t < NBANDS) {
        atomicAdd(&g_s1[img * NBANDS + t], hs1[t]);
        atomicAdd(&g_s2[img * NBANDS + t], hs2[t]);
        atomicMax(&g_mx[img * NBANDS + t], hmx[t]);
    }
}

// ---------------- kernel 4: features -> MLP -> LayerNorm ----------------
__device__ __forceinline__ float block_sum_256(float v, float* red, int t) {
#pragma unroll
    for (int o = 16; o; o >>= 1) v += __shfl_xor_sync(0xffffffffu, v, o);
    if ((t & 31) == 0) red[t >> 5] = v;
    __syncthreads();
    if (t < 8) {
        float w = red[t];
#pragma unroll
        for (int o = 4; o; o >>= 1) w += __shfl_xor_sync(0xffu, w, o);
        if (t == 0) red[0] = w;
    }
    __syncthreads();
    float r = red[0];
    __syncthreads();
    return r;
}

__global__ __launch_bounds__(256) void k_head(
    const float* __restrict__ W1, const float* __restrict__ b1,
    const float* __restrict__ W2, const float* __restrict__ b2,
    const float* __restrict__ gamma, const float* __restrict__ beta,
    float* __restrict__ out) {
    __shared__ float feat[FIN];
    __shared__ float h1[FEAT];
    __shared__ float red[8];
    int b = blockIdx.x;
    int t = threadIdx.x;
    if (t < FIN) {
        int k = t / 9;
        int rem = t - k * 9;
        int s = rem / 3;
        int c = rem - s * 3;
        int img = b * 3 + c;
        float cnt = g_cnt[k];
        float denom = cnt + 1e-8f;
        float s1 = g_s1[img * NBANDS + k];
        float s2 = g_s2[img * NBANDS + k];
        float mean = s1 / denom;
        float var = (s2 - 2.0f * mean * s1 + cnt * mean * mean) / denom;
        var = fmaxf(var, 0.0f);
        float mx = fmaxf(__uint_as_float(g_mx[img * NBANDS + k]), 0.0f);
        feat[t] = (s == 0) ? mean : ((s == 1) ? mx : sqrtf(var));
    }
    __syncthreads();
    float acc = b1[t];
#pragma unroll 4
    for (int i = 0; i < FIN; i++) acc = fmaf(feat[i], W1[i * FEAT + t], acc);
    acc = (acc >= 0.0f) ? acc : 0.2f * acc;
    h1[t] = acc;
    __syncthreads();
    float acc2 = b2[t];
#pragma unroll 4
    for (int i = 0; i < FEAT; i++) acc2 = fmaf(h1[i], W2[i * FEAT + t], acc2);
    float mu = block_sum_256(acc2, red, t) * (1.0f / 256.0f);
    float d = acc2 - mu;
    float va = block_sum_256(d * d, red, t) * (1.0f / 256.0f);
    out[b * FEAT + t] = d * rsqrtf(va + 1e-5f) * gamma[t] + beta[t];
}

// ---------------- launch ----------------
extern "C" void kernel_launch(void* const* d_in, const int* in_sizes, int n_in,
                              void* d_out, int out_size) {
    const float* x = (const float*)d_in[0];
    const float* W1 = (const float*)d_in[1];
    const float* b1 = (const float*)d_in[2];
    const float* W2 = (const float*)d_in[3];
    const float* b2 = (const float*)d_in[4];
    const float* gamma = (const float*)d_in[5];
    const float* beta = (const float*)d_in[6];
    float* out = (float*)d_out;
    (void)in_sizes; (void)n_in; (void)out_size;

    k_zero<<<6, 256>>>();
    k_counts<<<NH, 256>>>();
    k_rowfft<<<dim3(512, NIMG), 256>>>(x);
    k_colfft<<<dim3(129, NIMG), 512>>>();
    k_head<<<NB_B, 256>>>(W1, b1, W2, b2, gamma, beta, out);
}